// round 17
// baseline (speedup 1.0000x reference)
#include <cuda_runtime.h>
#include <cuda_fp16.h>
#include <cstdint>

// out[n,f] = (1/25) * sum_s relu( dot(E[nbr[n,s],:], W[f,:]) + b[f] )
// f16 HMMA (fp32 accum); table pre-converted to a __device__ f16 mirror.
// Gather: ONE cp.async.bulk (256B) per embedding row into a 272B-stride
// E tile, completion via mbarrier expect_tx. M=128 tiles (5 nodes),
// 256 thr = 8 warps (2m x 4n), 2 CTAs/SM. H (f16) aliases consumed E and is
// written with stmatrix.x4; mean-pool = MMA against block-(1/25) P.
// R17: W fragments for ks 0-3 cached in 32 persistent registers (W is
// kernel-constant), branchless neighbor load, 4-chunk convert_table.

#define S_SAMPLES 25
#define FDIM 128
#define TABLE_SIZE 100000
#define ROWS_PER_TILE 125
#define NODES_PER_TILE 5
#define M_PAD 128
#define BLOCK_THREADS 256
#define GRID_BLOCKS 296            // 2 per SM

#define ROW_STRIDE 272             // 256B data + 16B pad -> conflict-free ldmatrix
#define TILE_BYTES (M_PAD * ROW_STRIDE)   // 34816

#define E0_OFF 0
#define E1_OFF TILE_BYTES          // 34816
#define W_OFF  (2 * TILE_BYTES)    // 69632
#define B_OFF  (3 * TILE_BYTES)    // 104448 (bias 512B)
#define P_OFF  (B_OFF + 512)       // 104960 (pool A-frags 4KB)
#define MBAR_OFF (P_OFF + 4096)    // 109056 (2 x 8B)
#define SMEM_TOTAL (MBAR_OFF + 32)

__device__ int g_idx_is64;
__device__ uint4 g_tab16[TABLE_SIZE * 16];   // f16 table mirror, 256B rows

__device__ __forceinline__ uint32_t pack_h2(float a, float b) {
    uint32_t r;
    asm("cvt.rn.f16x2.f32 %0, %2, %1;" : "=r"(r) : "f"(a), "f"(b));
    return r;
}

// fp32 table -> f16 mirror (4 chunks/thread); block 0 thr 0 detects idx dtype.
__global__ void convert_table(const float4* __restrict__ table4,
                              const int* __restrict__ nb32) {
    if (blockIdx.x == 0 && threadIdx.x == 0) {
        int is64 = 1;
        #pragma unroll
        for (int i = 1; i < 64; i += 2) if (nb32[i] != 0) is64 = 0;
        g_idx_is64 = is64;
    }
    int base = blockIdx.x * (blockDim.x * 4) + threadIdx.x;
    #pragma unroll
    for (int k = 0; k < 4; ++k) {
        int i = base + k * blockDim.x;       // coalesced 16B chunks
        if (i < TABLE_SIZE * 16) {
            float4 v0 = __ldg(&table4[2 * i]);
            float4 v1 = __ldg(&table4[2 * i + 1]);
            uint4 w;
            w.x = pack_h2(v0.x, v0.y); w.y = pack_h2(v0.z, v0.w);
            w.z = pack_h2(v1.x, v1.y); w.w = pack_h2(v1.z, v1.w);
            g_tab16[i] = w;
        }
    }
}

// ---------------- helpers ----------------
__device__ __forceinline__ uint32_t smem_u32(const void* p) {
    uint32_t a;
    asm("{ .reg .u64 t; cvta.to.shared.u64 t, %1; cvt.u32.u64 %0, t; }" : "=r"(a) : "l"(p));
    return a;
}
__device__ __forceinline__ uint32_t ew(int row, int chunk) {
    return (uint32_t)row * ROW_STRIDE + (uint32_t)chunk * 16u;
}
__device__ __forceinline__ void ldm_x4(uint32_t* a, uint32_t addr) {
    asm volatile("ldmatrix.sync.aligned.m8n8.x4.shared.b16 {%0,%1,%2,%3}, [%4];"
                 : "=r"(a[0]), "=r"(a[1]), "=r"(a[2]), "=r"(a[3]) : "r"(addr));
}
__device__ __forceinline__ void ldm_x4_t(uint32_t* a, uint32_t addr) {
    asm volatile("ldmatrix.sync.aligned.m8n8.x4.trans.shared.b16 {%0,%1,%2,%3}, [%4];"
                 : "=r"(a[0]), "=r"(a[1]), "=r"(a[2]), "=r"(a[3]) : "r"(addr));
}
__device__ __forceinline__ void stm_x4(uint32_t addr, const uint32_t* r) {
    asm volatile("stmatrix.sync.aligned.m8n8.x4.shared.b16 [%0], {%1,%2,%3,%4};"
                 :: "r"(addr), "r"(r[0]), "r"(r[1]), "r"(r[2]), "r"(r[3]) : "memory");
}
__device__ __forceinline__ void mma_f16(float* d, const uint32_t* a,
                                        uint32_t b0, uint32_t b1) {
    asm volatile(
        "mma.sync.aligned.m16n8k16.row.col.f32.f16.f16.f32 "
        "{%0,%1,%2,%3}, {%4,%5,%6,%7}, {%8,%9}, {%0,%1,%2,%3};"
        : "+f"(d[0]), "+f"(d[1]), "+f"(d[2]), "+f"(d[3])
        : "r"(a[0]), "r"(a[1]), "r"(a[2]), "r"(a[3]), "r"(b0), "r"(b1));
}
__device__ __forceinline__ void mma_f16_zc(float* d, const uint32_t* a,
                                           uint32_t b0, uint32_t b1) {
    asm volatile(
        "mma.sync.aligned.m16n8k16.row.col.f32.f16.f16.f32 "
        "{%0,%1,%2,%3}, {%4,%5,%6,%7}, {%8,%9}, {%10,%10,%10,%10};"
        : "=f"(d[0]), "=f"(d[1]), "=f"(d[2]), "=f"(d[3])
        : "r"(a[0]), "r"(a[1]), "r"(a[2]), "r"(a[3]), "r"(b0), "r"(b1),
          "f"(0.0f));
}
__device__ __forceinline__ void mbar_wait(uint32_t mbar, uint32_t parity) {
    asm volatile(
        "{\n\t.reg .pred P;\n\t"
        "W%=:\n\tmbarrier.try_wait.parity.acquire.cta.shared::cta.b64 P, [%0], %1, 0x989680;\n\t"
        "@P bra D%=;\n\tbra W%=;\n\tD%=:\n\t}"
        :: "r"(mbar), "r"(parity) : "memory");
}

__global__ __launch_bounds__(BLOCK_THREADS, 2) void meanpool_kernel(
    const void* __restrict__ neighbors_raw,
    const float* __restrict__ W,
    const float* __restrict__ b,
    float* __restrict__ out,
    int n_nodes)
{
    extern __shared__ char s[];
    const uint32_t sbase = smem_u32(s);
    float* sB = (float*)(s + B_OFF);

    const int tid  = threadIdx.x;
    const int wid  = tid >> 5;
    const int lane = tid & 31;
    const int warp_m = wid & 1;      // 64-row block
    const int warp_n = wid >> 1;     // 32-col block

    // ---- mbarriers ----
    if (tid == 0) {
        asm volatile("mbarrier.init.shared.b64 [%0], %1;"
                     :: "r"(sbase + MBAR_OFF), "r"(BLOCK_THREADS) : "memory");
        asm volatile("mbarrier.init.shared.b64 [%0], %1;"
                     :: "r"(sbase + MBAR_OFF + 8), "r"(BLOCK_THREADS) : "memory");
    }

    // ---- Stage W (f16, padded rows) + bias; zero E pad rows 125-127 once ----
    const float4* __restrict__ W4 = (const float4*)W;
    for (int i = tid; i < FDIM * 16; i += BLOCK_THREADS) {
        int f = i >> 4, c = i & 15;
        float4 v0 = __ldg(&W4[f * 32 + 2 * c]);
        float4 v1 = __ldg(&W4[f * 32 + 2 * c + 1]);
        uint4 w;
        w.x = pack_h2(v0.x, v0.y); w.y = pack_h2(v0.z, v0.w);
        w.z = pack_h2(v1.x, v1.y); w.w = pack_h2(v1.z, v1.w);
        *(uint4*)(s + W_OFF + ew(f, c)) = w;
    }
    if (tid < (M_PAD - ROWS_PER_TILE) * 16 * 2) {   // 96 threads, once
        int buf = tid >= (M_PAD - ROWS_PER_TILE) * 16;
        int j = tid - buf * (M_PAD - ROWS_PER_TILE) * 16;
        int r = ROWS_PER_TILE + (j >> 4), c = j & 15;
        *(uint4*)(s + (buf ? E1_OFF : E0_OFF) + ew(r, c)) = make_uint4(0u, 0u, 0u, 0u);
    }
    if (tid < FDIM) sB[tid] = __ldg(&b[tid]);

    // ---- Build pool A-frags P (block value 1/25 -> scale folded in) ----
    {
        int kc = tid >> 5, ln = tid & 31;
        int r = ln >> 2, kb = kc * 16 + (ln & 3) * 2;
        const float pv = 1.0f / (float)S_SAMPLES;
        uint4 pf;
        uint32_t* pp = (uint32_t*)&pf;
        #pragma unroll
        for (int j = 0; j < 4; ++j) {
            int row = r + ((j & 1) << 3);
            int k = kb + ((j >> 1) << 3);
            float v0 = (row < NODES_PER_TILE && k >= 25 * row && k < 25 * row + 25) ? pv : 0.f;
            float v1 = (row < NODES_PER_TILE && k + 1 >= 25 * row && k + 1 < 25 * row + 25) ? pv : 0.f;
            pp[j] = pack_h2(v0, v1);
        }
        *(uint4*)(s + P_OFF + tid * 16) = pf;
    }
    __syncthreads();   // mbarrier init + staging visible

    // per-thread bias registers
    float bb[4][2];
    #pragma unroll
    for (int fn = 0; fn < 4; ++fn) {
        int c0 = warp_n * 32 + fn * 8 + (lane & 3) * 2;
        bb[fn][0] = sB[c0];
        bb[fn][1] = sB[c0 + 1];
    }

    // branchless neighbor base: int64 little-endian low word == value
    const char* __restrict__ nbase = (const char*)neighbors_raw;
    const int idx_shift = 2 + g_idx_is64;    // log2 element stride

    const int total_rows = n_nodes * S_SAMPLES;          // <= 1.25M, int-safe
    const int n_tiles = (total_rows + ROWS_PER_TILE - 1) / ROWS_PER_TILE;

    auto load_idx = [&](int row_base) -> int {
        if (row_base < total_rows && tid < ROWS_PER_TILE) {
            int gr = row_base + tid;
            int nb = 0;
            if (gr < total_rows)
                nb = __ldg((const int*)(nbase + ((size_t)gr << idx_shift)));
            nb = nb < 0 ? 0 : (nb >= TABLE_SIZE ? TABLE_SIZE - 1 : nb);
            return nb;
        }
        return -1;
    };
    auto issue_copy = [&](uint32_t ebase, uint32_t mbar, int pidx) {
        if (pidx >= 0) {
            asm volatile("mbarrier.arrive.expect_tx.shared.b64 _, [%0], 256;"
                         :: "r"(mbar) : "memory");
            asm volatile(
                "cp.async.bulk.shared::cluster.global.mbarrier::complete_tx::bytes "
                "[%0], [%1], 256, [%2];"
                :: "r"(ebase + (uint32_t)tid * ROW_STRIDE),
                   "l"((const char*)g_tab16 + (long long)pidx * 256), "r"(mbar) : "memory");
        } else {
            asm volatile("mbarrier.arrive.shared.b64 _, [%0];" :: "r"(mbar) : "memory");
        }
    };

    // ---- prologue: prefetch t0 -> E0/mbar0, t1 -> E1/mbar1 ----
    issue_copy(sbase + E0_OFF, sbase + MBAR_OFF,
               load_idx(blockIdx.x * ROWS_PER_TILE));
    issue_copy(sbase + E1_OFF, sbase + MBAR_OFF + 8,
               load_idx((blockIdx.x + GRID_BLOCKS) * ROWS_PER_TILE));

    // per-lane ldmatrix address components
    const int a_row = (lane & 15);
    const int a_kc  = lane >> 4;
    const int b_n   = (lane & 7);
    const int b_kc  = (lane >> 3) & 1;
    const int b_fs  = lane >> 4;
    const int p_row = ((lane >> 3) & 1) * 8 + (lane & 7);
    const int p_cc  = ((wid * 16) + ((lane >> 4) << 3)) >> 3;
    const uint32_t stm_lane = (uint32_t)(lane & 7) * ROW_STRIDE +
                              (uint32_t)(lane >> 3) * 16u +
                              (uint32_t)warp_m * 64u * ROW_STRIDE +
                              (uint32_t)warp_n * 64u;

    const uint32_t b_base = sbase + W_OFF + ew(warp_n * 32 + b_fs * 8 + b_n, b_kc);

    // ---- persistent W fragments for ks 0..3 (W is kernel-constant) ----
    uint32_t bWr[32];
    #pragma unroll
    for (int ks = 0; ks < 4; ++ks) {
        ldm_x4(bWr + ks * 8,     b_base + (uint32_t)(ks * 32));
        ldm_x4(bWr + ks * 8 + 4, b_base + 16u * ROW_STRIDE + (uint32_t)(ks * 32));
    }

    int par0 = 0, par1 = 0;
    int cur = 0;
    for (int tile = blockIdx.x; tile < n_tiles; tile += GRID_BLOCKS, cur ^= 1) {
        const uint32_t ebase = sbase + (cur ? E1_OFF : E0_OFF);
        const uint32_t mbar  = sbase + MBAR_OFF + (cur ? 8 : 0);

        // hoist next-next tile's gather indices (LDG latency hides under MMA)
        const int pidx = load_idx((tile + 2 * GRID_BLOCKS) * ROWS_PER_TILE);

        // wait for this buffer's gather
        if (cur) { mbar_wait(mbar, par1); par1 ^= 1; }
        else     { mbar_wait(mbar, par0); par0 ^= 1; }

        // ---- main HMMA: 64x32 per warp ----
        float acc[4][4][4];
        const uint32_t a_base = ebase + ew(warp_m * 64 + a_row, a_kc);

        {   // ks = 0: initialize accumulators via c=0 (bWr)
            #pragma unroll
            for (int fm = 0; fm < 4; ++fm) {
                uint32_t aF[4];
                ldm_x4(aF, a_base + (uint32_t)(fm * 16) * ROW_STRIDE);
                #pragma unroll
                for (int fn = 0; fn < 4; ++fn)
                    mma_f16_zc(acc[fm][fn], aF, bWr[fn * 2], bWr[fn * 2 + 1]);
            }
        }
        #pragma unroll
        for (int ks = 1; ks < 4; ++ks) {     // ks 1..3 from registers
            #pragma unroll
            for (int fm = 0; fm < 4; ++fm) {
                uint32_t aF[4];
                ldm_x4(aF, a_base + (uint32_t)(fm * 16) * ROW_STRIDE + (uint32_t)(ks * 32));
                #pragma unroll
                for (int fn = 0; fn < 4; ++fn)
                    mma_f16(acc[fm][fn], aF, bWr[ks * 8 + fn * 2], bWr[ks * 8 + fn * 2 + 1]);
            }
        }
        #pragma unroll
        for (int ks = 4; ks < 8; ++ks) {     // ks 4..7 from smem
            uint32_t bW[8];
            ldm_x4(bW,     b_base + (uint32_t)(ks * 32));
            ldm_x4(bW + 4, b_base + 16u * ROW_STRIDE + (uint32_t)(ks * 32));
            #pragma unroll
            for (int fm = 0; fm < 4; ++fm) {
                uint32_t aF[4];
                ldm_x4(aF, a_base + (uint32_t)(fm * 16) * ROW_STRIDE + (uint32_t)(ks * 32));
                #pragma unroll
                for (int fn = 0; fn < 4; ++fn)
                    mma_f16(acc[fm][fn], aF, bW[fn * 2], bW[fn * 2 + 1]);
            }
        }

        // own-group E reads done (rows 64*warp_m..+63 private to group)
        asm volatile("bar.sync %0, 128;" :: "r"(1 + warp_m) : "memory");

        // ---- bias+relu -> H via stmatrix (f16, aliases E[cur]) ----
        #pragma unroll
        for (int fm = 0; fm < 4; ++fm) {
            uint32_t h0[4], h1[4];
            #pragma unroll
            for (int fn = 0; fn < 4; ++fn) {
                h0[fn] = pack_h2(fmaxf(acc[fm][fn][0] + bb[fn][0], 0.f),
                                 fmaxf(acc[fm][fn][1] + bb[fn][1], 0.f));
                h1[fn] = pack_h2(fmaxf(acc[fm][fn][2] + bb[fn][0], 0.f),
                                 fmaxf(acc[fm][fn][3] + bb[fn][1], 0.f));
            }
            uint32_t a0 = ebase + stm_lane + (uint32_t)(fm * 16) * ROW_STRIDE;
            stm_x4(a0, h0);
            stm_x4(a0 + 8u * ROW_STRIDE, h1);
        }
        __syncthreads();   // full H visible to every warp's pool

        // ---- pool MMA: D[5x16 per warp] = P @ H (scale folded into P) ----
        {
            float dp0[4] = {0.f, 0.f, 0.f, 0.f}, dp1[4] = {0.f, 0.f, 0.f, 0.f};
            #pragma unroll
            for (int kc = 0; kc < 8; ++kc) {
                uint32_t pf[4], bf[4];
                *(uint4*)pf = *(const uint4*)(s + P_OFF + ((kc << 5) + lane) * 16);
                ldm_x4_t(bf, ebase + ew(kc * 16 + p_row, p_cc));
                mma_f16(dp0, pf, bf[0], bf[1]);
                mma_f16(dp1, pf, bf[2], bf[3]);
            }
            int g = lane >> 2;
            if (g < NODES_PER_TILE) {
                int n = tile * NODES_PER_TILE + g;
                if (n < n_nodes) {
                    int cb = n * FDIM + wid * 16 + (lane & 3) * 2;
                    *(float2*)&out[cb]     = make_float2(dp0[0], dp0[1]);
                    *(float2*)&out[cb + 8] = make_float2(dp1[0], dp1[1]);
                }
            }
        }
        __syncthreads();   // pool reads done before bulk copies overwrite

        // ---- issue prefetch for tile t+2 (indices already in regs) ----
        issue_copy(ebase, mbar, pidx);
    }
}

extern "C" void kernel_launch(void* const* d_in, const int* in_sizes, int n_in,
                              void* d_out, int out_size) {
    const void*  neighbors = d_in[0];
    const float* emb_table = (const float*)d_in[1];
    const float* W         = (const float*)d_in[2];
    const float* b         = (const float*)d_in[3];
    float*       out       = (float*)d_out;

    const int n_nodes = in_sizes[0] / S_SAMPLES;

    cudaFuncSetAttribute(meanpool_kernel,
                         cudaFuncAttributeMaxDynamicSharedMemorySize, SMEM_TOTAL);

    convert_table<<<(TABLE_SIZE * 16 + 1023) / 1024, 256>>>((const float4*)emb_table,
                                                            (const int*)neighbors);
    meanpool_kernel<<<GRID_BLOCKS, BLOCK_THREADS, SMEM_TOTAL>>>(
        neighbors, W, b, out, n_nodes);
}